// round 4
// baseline (speedup 1.0000x reference)
#include <cuda_runtime.h>
#include <cstdint>
#include <cstddef>

#define K_DIM 4096
#define N_DIM 11008
#define M_DIM 8192

#define BM 128
#define BN 256
#define BK 32
#define KT (K_DIM / BK)                 // 128 k-chunks
#define NSTAGE 3
#define PADK 36                         // floats per smem row (32 + 4 pad): conflict-free
#define A_FLOATS (BM * PADK)            // 4608
#define B_FLOATS (BN * PADK)            // 9216
#define STAGE_FLOATS (A_FLOATS + B_FLOATS)
#define STAGE_BYTES (STAGE_FLOATS * 4)  // 55296
#define SMEM_TOTAL (NSTAGE * STAGE_BYTES) // 165888 B

// Scratch (allocation-free rule: __device__ globals)
__device__ float g_Wt[(size_t)N_DIM * (size_t)K_DIM];   // W^T [N, K], tf32-rounded
__device__ float g_Xt[(size_t)M_DIM * (size_t)K_DIM];   // X   [M, K], tf32-rounded

__device__ __forceinline__ float to_tf32(float f) {
    uint32_t u;
    asm("cvt.rna.tf32.f32 %0, %1;" : "=r"(u) : "f"(f));
    return __uint_as_float(u);
}

#define CPA16(s, g) asm volatile("cp.async.cg.shared.global [%0], [%1], 16;" :: "r"(s), "l"(g) : "memory")
#define CP_COMMIT() asm volatile("cp.async.commit_group;" ::: "memory")
#define CP_WAIT1()  asm volatile("cp.async.wait_group 1;" ::: "memory")

__device__ __forceinline__ uint32_t smem_u32(const void* p) {
    uint32_t a;
    asm("{ .reg .u64 t; cvta.to.shared.u64 t, %1; cvt.u32.u64 %0, t; }" : "=r"(a) : "l"(p));
    return a;
}

__device__ __forceinline__ void mma_tf32(float* c, const uint32_t* a, const uint32_t* b) {
    asm volatile(
        "mma.sync.aligned.m16n8k8.row.col.f32.tf32.tf32.f32 "
        "{%0,%1,%2,%3}, {%4,%5,%6,%7}, {%8,%9}, {%0,%1,%2,%3};"
        : "+f"(c[0]), "+f"(c[1]), "+f"(c[2]), "+f"(c[3])
        : "r"(a[0]), "r"(a[1]), "r"(a[2]), "r"(a[3]), "r"(b[0]), "r"(b[1]));
}

// ------------- kernel 1: dequant qweight -> W^T [N, K], tf32-rounded -------------
__global__ void dequant_kernel(const int* __restrict__ qw, const int* __restrict__ qz,
                               const float* __restrict__ sc) {
    int t = blockIdx.x * blockDim.x + threadIdx.x;     // (K/8)*N threads exactly
    int kb = t / N_DIM;                                // packed k-row (8 k's per int32)
    int n  = t - kb * N_DIM;
    uint32_t w32 = (uint32_t)qw[(size_t)kb * N_DIM + n];
    int g = kb >> 4;                                   // k-group = (kb*8)/128
    uint32_t zw = (uint32_t)qz[g * (N_DIM / 8) + (n >> 3)];
    int z = (int)((zw >> ((n & 7) * 4)) & 0xFu) + 1;   // GPTQ zero+1
    float s = sc[(size_t)g * N_DIM + n];
    float v[8];
#pragma unroll
    for (int j = 0; j < 8; j++) {
        int w = (int)((w32 >> (4 * j)) & 0xFu);
        v[j] = to_tf32((float)(w - z) * s);
    }
    float4* dst = (float4*)(g_Wt + (size_t)n * K_DIM + (size_t)kb * 8);
    dst[0] = make_float4(v[0], v[1], v[2], v[3]);
    dst[1] = make_float4(v[4], v[5], v[6], v[7]);
}

// ------------- kernel 2: x -> tf32-rounded copy -------------
__global__ void cvt_x_kernel(const float4* __restrict__ x) {
    int t = blockIdx.x * blockDim.x + threadIdx.x;     // M*K/4 threads exactly
    float4 a = x[t];
    a.x = to_tf32(a.x); a.y = to_tf32(a.y); a.z = to_tf32(a.z); a.w = to_tf32(a.w);
    ((float4*)g_Xt)[t] = a;
}

// ------------- kernel 3: mma.sync tf32 GEMM  out[M,N] = X @ W -------------
// 256 threads = 8 warps (2 in M x 4 in N), each warp a 64x64 tile.
__global__ __launch_bounds__(256, 1) void gemm_kernel(float* __restrict__ out) {
    extern __shared__ __align__(128) float smem[];
    const int tid = threadIdx.x;
    const int wid = tid >> 5;
    const int lid = tid & 31;
    const int grp = lid >> 2;       // 0..7
    const int tg  = lid & 3;        // 0..3
    const int warpM = wid & 1;      // 0..1
    const int warpN = wid >> 1;     // 0..3
    const int nTile = blockIdx.x;   // 43
    const int mTile = blockIdx.y;   // 64

    const uint32_t smem_addr = smem_u32(smem);

    // cp.async slot precompute: 3072 16B chunks per stage, 12 per thread (4 A + 8 B)
    uint32_t aS[4]; const float* aG[4];
#pragma unroll
    for (int i = 0; i < 4; i++) {
        int q = tid + 256 * i;                  // 0..1023 -> A chunks
        int row = q >> 3, c = q & 7;
        aS[i] = (uint32_t)((row * PADK + c * 4) * 4);
        aG[i] = g_Xt + (size_t)(mTile * BM + row) * K_DIM + c * 4;
    }
    uint32_t bS[8]; const float* bG[8];
#pragma unroll
    for (int i = 0; i < 8; i++) {
        int q = tid + 256 * i;                  // 0..2047 -> B chunks
        int row = q >> 3, c = q & 7;
        bS[i] = (uint32_t)((A_FLOATS + row * PADK + c * 4) * 4);
        bG[i] = g_Wt + (size_t)(nTile * BN + row) * K_DIM + c * 4;
    }

    // Prologue: fill stages 0,1
#pragma unroll
    for (int p = 0; p < NSTAGE - 1; p++) {
        uint32_t base = smem_addr + p * STAGE_BYTES;
        int koff = p * BK;
#pragma unroll
        for (int i = 0; i < 4; i++) CPA16(base + aS[i], aG[i] + koff);
#pragma unroll
        for (int i = 0; i < 8; i++) CPA16(base + bS[i], bG[i] + koff);
        CP_COMMIT();
    }

    float acc[4][8][4];
#pragma unroll
    for (int i = 0; i < 4; i++)
#pragma unroll
        for (int j = 0; j < 8; j++)
#pragma unroll
            for (int r = 0; r < 4; r++) acc[i][j][r] = 0.0f;

    // Fragment base offsets (float indices within a stage)
    const int aBase = (warpM * 64 + grp) * PADK + tg;            // + i*16*PADK, +8*PADK, +4
    const int bBase = A_FLOATS + (warpN * 64 + grp) * PADK + tg; // + j*8*PADK, +4

    for (int kt = 0; kt < KT; kt++) {
        CP_WAIT1();                       // stage kt resident
        __syncthreads();                  // all warps past compute of kt-1

        int kl = kt + NSTAGE - 1;
        if (kl < KT) {
            uint32_t base = smem_addr + (kl % NSTAGE) * STAGE_BYTES;
            int koff = kl * BK;
#pragma unroll
            for (int i = 0; i < 4; i++) CPA16(base + aS[i], aG[i] + koff);
#pragma unroll
            for (int i = 0; i < 8; i++) CPA16(base + bS[i], bG[i] + koff);
        }
        CP_COMMIT();                      // empty near tail keeps counts uniform

        const float* st = smem + (kt % NSTAGE) * STAGE_FLOATS;
#pragma unroll
        for (int ks = 0; ks < 4; ks++) {
            const int k0 = ks * 8;
            uint32_t aR[16], bR[16];
#pragma unroll
            for (int i = 0; i < 4; i++) {
                const float* p = st + aBase + i * 16 * PADK + k0;
                aR[i * 4 + 0] = __float_as_uint(p[0]);
                aR[i * 4 + 1] = __float_as_uint(p[8 * PADK]);
                aR[i * 4 + 2] = __float_as_uint(p[4]);
                aR[i * 4 + 3] = __float_as_uint(p[8 * PADK + 4]);
            }
#pragma unroll
            for (int j = 0; j < 8; j++) {
                const float* p = st + bBase + j * 8 * PADK + k0;
                bR[j * 2 + 0] = __float_as_uint(p[0]);
                bR[j * 2 + 1] = __float_as_uint(p[4]);
            }
#pragma unroll
            for (int i = 0; i < 4; i++)
#pragma unroll
                for (int j = 0; j < 8; j++)
                    mma_tf32(acc[i][j], aR + i * 4, bR + j * 2);
        }
    }

    // Epilogue: direct STG from accumulators
    const size_t mBase = (size_t)mTile * BM + warpM * 64 + grp;
    const size_t nBase = (size_t)nTile * BN + warpN * 64 + tg * 2;
#pragma unroll
    for (int i = 0; i < 4; i++) {
        size_t r0 = mBase + i * 16;
#pragma unroll
        for (int j = 0; j < 8; j++) {
            size_t cc = nBase + j * 8;
            *(float2*)(out + r0 * N_DIM + cc)       = make_float2(acc[i][j][0], acc[i][j][1]);
            *(float2*)(out + (r0 + 8) * N_DIM + cc) = make_float2(acc[i][j][2], acc[i][j][3]);
        }
    }
}

// ---------------- launch ----------------
extern "C" void kernel_launch(void* const* d_in, const int* in_sizes, int n_in,
                              void* d_out, int out_size) {
    const float* x  = (const float*)d_in[0];
    const int*   qw = (const int*)d_in[1];
    const int*   qz = (const int*)d_in[2];
    const float* sc = (const float*)d_in[3];
    float* out = (float*)d_out;

    cudaFuncSetAttribute(gemm_kernel, cudaFuncAttributeMaxDynamicSharedMemorySize, SMEM_TOTAL);

    dequant_kernel<<<(K_DIM / 8) * N_DIM / 256, 256>>>(qw, qz, sc);
    cvt_x_kernel<<<(int)((size_t)M_DIM * K_DIM / 4 / 256), 256>>>((const float4*)x);

    dim3 grid(N_DIM / BN, M_DIM / BM);   // 43 x 64
    gemm_kernel<<<grid, 256, SMEM_TOTAL>>>(out);
}

// round 6
// speedup vs baseline: 1.9431x; 1.9431x over previous
#include <cuda_runtime.h>
#include <cstdint>
#include <cstddef>

#define K_DIM 4096
#define N_DIM 11008
#define M_DIM 8192

#define BM 128
#define BN 256
#define BK 32
#define KT (K_DIM / BK)                 // 128 k-chunks
#define NSTAGE 4
#define A_F4 1024                       // float4 per stage for A (128 rows x 32 k)
#define B_F4 2048                       // float4 per stage for B (256 rows x 32 k)
#define STAGE_F4 (A_F4 + B_F4)          // 3072
#define STAGE_BYTES (STAGE_F4 * 16)     // 49152
#define SMEM_TOTAL (NSTAGE * STAGE_BYTES) // 196608 B

#define MBAND 16                        // mTiles per band (L2 swizzle)
#define NT (N_DIM / BN)                 // 43
#define MT (M_DIM / BM)                 // 64

// Scratch (allocation-free rule: __device__ globals), PERMUTED layouts:
// g_Wt: per n-row, k packed as float4 {k16*16+tg, +4, +8, +12}; f4idx = n*1024 + k16*4 + tg
// g_Xt: per row-pair (r, r+8 within 16-row groups): f4 {a(ra,k),a(rb,k),a(ra,k+4),a(rb,k+4)};
//       f4idx = pair*2048 + k8*4 + tg   (pair = (r/16)*8 + r%8)
__device__ float4 g_Wt[(size_t)N_DIM * (K_DIM / 4)];
__device__ float4 g_Xt[(size_t)(M_DIM / 2) * (K_DIM / 2)];

__device__ __forceinline__ float to_tf32(float f) {
    uint32_t u;
    asm("cvt.rna.tf32.f32 %0, %1;" : "=r"(u) : "f"(f));
    return __uint_as_float(u);
}

#define CPA16(s, g) asm volatile("cp.async.cg.shared.global [%0], [%1], 16;" :: "r"(s), "l"(g) : "memory")
#define CP_COMMIT() asm volatile("cp.async.commit_group;" ::: "memory")
#define CP_WAIT2()  asm volatile("cp.async.wait_group 2;" ::: "memory")

__device__ __forceinline__ uint32_t smem_u32(const void* p) {
    uint32_t a;
    asm("{ .reg .u64 t; cvta.to.shared.u64 t, %1; cvt.u32.u64 %0, t; }" : "=r"(a) : "l"(p));
    return a;
}

__device__ __forceinline__ void mma_tf32(float* c, const float4& a, float b0, float b1) {
    asm volatile(
        "mma.sync.aligned.m16n8k8.row.col.f32.tf32.tf32.f32 "
        "{%0,%1,%2,%3}, {%4,%5,%6,%7}, {%8,%9}, {%0,%1,%2,%3};"
        : "+f"(c[0]), "+f"(c[1]), "+f"(c[2]), "+f"(c[3])
        : "r"(__float_as_uint(a.x)), "r"(__float_as_uint(a.y)),
          "r"(__float_as_uint(a.z)), "r"(__float_as_uint(a.w)),
          "r"(__float_as_uint(b0)), "r"(__float_as_uint(b1)));
}

// ------- kernel 1: dequant qweight -> g_Wt (permuted, tf32-rounded) -------
// thread t: n = t % N, k16 = t / N. Writes 64B contiguous (4 float4).
__global__ void dequant_kernel(const int* __restrict__ qw, const int* __restrict__ qz,
                               const float* __restrict__ sc) {
    int t = blockIdx.x * blockDim.x + threadIdx.x;   // N * (K/16) threads
    int n   = t % N_DIM;
    int k16 = t / N_DIM;
    uint32_t w0 = (uint32_t)qw[(size_t)(2 * k16) * N_DIM + n];
    uint32_t w1 = (uint32_t)qw[(size_t)(2 * k16 + 1) * N_DIM + n];
    int g = k16 >> 3;                                // k16*16 / 128
    uint32_t zw = (uint32_t)qz[g * (N_DIM / 8) + (n >> 3)];
    int z = (int)((zw >> ((n & 7) * 4)) & 0xFu) + 1;
    float s = sc[(size_t)g * N_DIM + n];
    float v[16];
#pragma unroll
    for (int j = 0; j < 8; j++) {
        v[j]     = to_tf32((float)((int)((w0 >> (4 * j)) & 0xFu) - z) * s);
        v[j + 8] = to_tf32((float)((int)((w1 >> (4 * j)) & 0xFu) - z) * s);
    }
    float4* dst = g_Wt + (size_t)n * 1024 + (size_t)k16 * 4;
#pragma unroll
    for (int tg = 0; tg < 4; tg++)
        dst[tg] = make_float4(v[tg], v[tg + 4], v[tg + 8], v[tg + 12]);
}

// ------- kernel 2: x -> g_Xt (pair-permuted, tf32-rounded) -------
// thread t: k8 = t % 512, pair = t / 512.
__global__ void cvt_x_kernel(const float4* __restrict__ x) {
    int t = blockIdx.x * blockDim.x + threadIdx.x;   // (M/2)*(K/8) threads
    int k8   = t & 511;
    int pair = t >> 9;
    int ra = (pair >> 3) * 16 + (pair & 7);
    int rb = ra + 8;
    float4 a0 = x[(size_t)ra * (K_DIM / 4) + k8 * 2];
    float4 a1 = x[(size_t)ra * (K_DIM / 4) + k8 * 2 + 1];
    float4 b0 = x[(size_t)rb * (K_DIM / 4) + k8 * 2];
    float4 b1 = x[(size_t)rb * (K_DIM / 4) + k8 * 2 + 1];
    float av[8] = {a0.x, a0.y, a0.z, a0.w, a1.x, a1.y, a1.z, a1.w};
    float bv[8] = {b0.x, b0.y, b0.z, b0.w, b1.x, b1.y, b1.z, b1.w};
    float4* dst = g_Xt + (size_t)pair * 2048 + (size_t)k8 * 4;
#pragma unroll
    for (int tg = 0; tg < 4; tg++)
        dst[tg] = make_float4(to_tf32(av[tg]), to_tf32(bv[tg]),
                              to_tf32(av[tg + 4]), to_tf32(bv[tg + 4]));
}

// ------- kernel 3: mma.sync tf32 GEMM  out[M,N] = X @ W -------
__global__ __launch_bounds__(256, 1) void gemm_kernel(float* __restrict__ out) {
    extern __shared__ __align__(16) char smem[];
    float4* sm4 = (float4*)smem;
    const uint32_t smem_addr = smem_u32(smem);
    const int tid = threadIdx.x;
    const int wid = tid >> 5;
    const int lid = tid & 31;
    const int grp = lid >> 2;       // 0..7
    const int tg  = lid & 3;        // 0..3
    const int P   = grp & 1;        // parity for XOR swizzle
    const int warpM = wid & 1;
    const int warpN = wid >> 1;

    // band swizzle: 16 mTiles x 43 nTiles per band
    const int band = blockIdx.x / (MBAND * NT);
    const int rem  = blockIdx.x % (MBAND * NT);
    const int nTile = rem / MBAND;
    const int mTile = band * MBAND + (rem % MBAND);

    // cp.async slots: 3072 f4/stage; thread owns 4 A + 8 B
    const float4* aG[4]; uint32_t aS[4];
#pragma unroll
    for (int ii = 0; ii < 4; ii++) {
        int q = tid + 256 * ii;              // 0..1023
        int p = q >> 4, sP = q & 15;
        int ksE = (sP >> 2) ^ (p & 1), tg4 = sP & 3;
        aG[ii] = g_Xt + (size_t)(mTile * 64 + p) * 2048 + ksE * 4 + tg4;
        aS[ii] = (uint32_t)(q * 16);
    }
    const float4* bG[8]; uint32_t bS[8];
#pragma unroll
    for (int ii = 0; ii < 8; ii++) {
        int q = tid + 256 * ii;              // 0..2047
        int nL = q >> 3, sP = q & 7;
        int k16E = (sP >> 2) ^ (nL & 1), tg4 = sP & 3;
        bG[ii] = g_Wt + (size_t)(nTile * 256 + nL) * 1024 + k16E * 4 + tg4;
        bS[ii] = (uint32_t)(A_F4 * 16 + q * 16);
    }

    // Prologue: stages 0..2
#pragma unroll
    for (int p = 0; p < NSTAGE - 1; p++) {
        uint32_t base = smem_addr + p * STAGE_BYTES;
#pragma unroll
        for (int i = 0; i < 4; i++) CPA16(base + aS[i], aG[i] + (size_t)p * 16);
#pragma unroll
        for (int i = 0; i < 8; i++) CPA16(base + bS[i], bG[i] + (size_t)p * 8);
        CP_COMMIT();
    }

    float acc[4][8][4];
#pragma unroll
    for (int i = 0; i < 4; i++)
#pragma unroll
        for (int j = 0; j < 8; j++)
#pragma unroll
            for (int r = 0; r < 4; r++) acc[i][j][r] = 0.0f;

    // fragment f4 indices within a stage
    int aIdx[4], bIdx[8];
#pragma unroll
    for (int i = 0; i < 4; i++)
        aIdx[i] = (warpM * 32 + i * 8 + grp) * 16 + tg;   // + (ks^P)*4
#pragma unroll
    for (int j = 0; j < 8; j++)
        bIdx[j] = A_F4 + (warpN * 64 + j * 8 + grp) * 8 + tg;  // + (k16^P)*4

    for (int kt = 0; kt < KT; kt++) {
        CP_WAIT2();                   // stage kt resident
        __syncthreads();              // all warps done with stage kt-1 (buffer reuse)

        int kl = kt + NSTAGE - 1;
        if (kl < KT) {
            uint32_t base = smem_addr + (kl & 3) * STAGE_BYTES;
#pragma unroll
            for (int i = 0; i < 4; i++) CPA16(base + aS[i], aG[i] + (size_t)kl * 16);
#pragma unroll
            for (int i = 0; i < 8; i++) CPA16(base + bS[i], bG[i] + (size_t)kl * 8);
        }
        CP_COMMIT();

        const float4* st = sm4 + (kt & 3) * STAGE_F4;
#pragma unroll
        for (int k16L = 0; k16L < 2; k16L++) {
            float4 bf[8];
            const int bo = ((k16L ^ P) << 2);
#pragma unroll
            for (int j = 0; j < 8; j++) bf[j] = st[bIdx[j] + bo];
#pragma unroll
            for (int h = 0; h < 2; h++) {
                const int ks = k16L * 2 + h;
                const int ao = ((ks ^ P) << 2);
                float4 af[4];
#pragma unroll
                for (int i = 0; i < 4; i++) af[i] = st[aIdx[i] + ao];
#pragma unroll
                for (int i = 0; i < 4; i++)
#pragma unroll
                    for (int j = 0; j < 8; j++) {
                        if (h == 0) mma_tf32(acc[i][j], af[i], bf[j].x, bf[j].y);
                        else        mma_tf32(acc[i][j], af[i], bf[j].z, bf[j].w);
                    }
            }
        }
    }

    // Epilogue: direct STG from accumulators
    const size_t mBase = (size_t)mTile * BM + warpM * 64 + grp;
    const size_t nBase = (size_t)nTile * BN + warpN * 64 + tg * 2;
#pragma unroll
    for (int i = 0; i < 4; i++) {
        size_t r0 = mBase + i * 16;
#pragma unroll
        for (int j = 0; j < 8; j++) {
            size_t cc = nBase + j * 8;
            *(float2*)(out + r0 * N_DIM + cc)       = make_float2(acc[i][j][0], acc[i][j][1]);
            *(float2*)(out + (r0 + 8) * N_DIM + cc) = make_float2(acc[i][j][2], acc[i][j][3]);
        }
    }
}

// ---------------- launch ----------------
extern "C" void kernel_launch(void* const* d_in, const int* in_sizes, int n_in,
                              void* d_out, int out_size) {
    const float* x  = (const float*)d_in[0];
    const int*   qw = (const int*)d_in[1];
    const int*   qz = (const int*)d_in[2];
    const float* sc = (const float*)d_in[3];
    float* out = (float*)d_out;

    cudaFuncSetAttribute(gemm_kernel, cudaFuncAttributeMaxDynamicSharedMemorySize, SMEM_TOTAL);

    dequant_kernel<<<N_DIM * (K_DIM / 16) / 256, 256>>>(qw, qz, sc);
    cvt_x_kernel<<<(M_DIM / 2) * (K_DIM / 8) / 256, 256>>>((const float4*)x);

    gemm_kernel<<<MT * NT, 256, SMEM_TOTAL>>>(out);
}

// round 8
// speedup vs baseline: 3.8775x; 1.9955x over previous
#include <cuda_runtime.h>
#include <cuda_fp16.h>
#include <cstdint>
#include <cstddef>

#define K_DIM 4096
#define N_DIM 11008
#define M_DIM 8192

#define BM 128
#define BN 256
#define BK 64
#define KT (K_DIM / BK)                  // 64 k-chunks
#define NSTAGE 4
#define A_BYTES (BM * BK * 2)            // 16384
#define B_BYTES (BN * BK * 2)            // 32768
#define STAGE_BYTES (A_BYTES + B_BYTES)  // 49152
#define SMEM_TOTAL (NSTAGE * STAGE_BYTES) // 196608
#define A_U4 (A_BYTES / 16)              // 1024 uint4

#define MBAND 16
#define NT (N_DIM / BN)                  // 43
#define MT (M_DIM / BM)                  // 64

// Scratch (__device__ globals; allocation-free rule). PRE-PACKED fp16 layouts:
// g_W: per n-oct (8 n), per kb32, 32 uint4; unit(oct,kb32,grp=n%8,tg) at byte
//      oct*65536 + kb32*512 + grp*64 + tg*16 ; uint4 = {b0,b1(k16_0), b0,b1(k16_1)}
// g_X: per 16-row panel, per k16, 8 grp x 4 tg uint4; byte
//      panel*131072 + k16*512 + grp*64 + tg*16 ; uint4 = {a0,a1,a2,a3} (rows grp/grp+8)
__device__ __half g_W[(size_t)N_DIM * K_DIM];
__device__ __half g_X[(size_t)M_DIM * K_DIM];

#define CPA16(s, g) asm volatile("cp.async.cg.shared.global [%0], [%1], 16;" :: "r"(s), "l"(g) : "memory")
#define CP_COMMIT() asm volatile("cp.async.commit_group;" ::: "memory")
#define CP_WAIT2()  asm volatile("cp.async.wait_group 2;" ::: "memory")

__device__ __forceinline__ uint32_t smem_u32(const void* p) {
    uint32_t a;
    asm("{ .reg .u64 t; cvta.to.shared.u64 t, %1; cvt.u32.u64 %0, t; }" : "=r"(a) : "l"(p));
    return a;
}

__device__ __forceinline__ uint32_t h2(float lo, float hi) {
    __half2 h = __floats2half2_rn(lo, hi);
    return *reinterpret_cast<uint32_t*>(&h);
}

__device__ __forceinline__ void mma_f16(float* c, const uint4& a, uint32_t b0, uint32_t b1) {
    asm volatile(
        "mma.sync.aligned.m16n8k16.row.col.f32.f16.f16.f32 "
        "{%0,%1,%2,%3}, {%4,%5,%6,%7}, {%8,%9}, {%0,%1,%2,%3};"
        : "+f"(c[0]), "+f"(c[1]), "+f"(c[2]), "+f"(c[3])
        : "r"(a.x), "r"(a.y), "r"(a.z), "r"(a.w), "r"(b0), "r"(b1));
}

// ------- kernel 1: dequant qweight -> g_W (packed fp16 B units) -------
__global__ __launch_bounds__(256) void dequant_kernel(const int* __restrict__ qw,
                                                      const int* __restrict__ qz,
                                                      const float* __restrict__ sc) {
    int t = blockIdx.x * blockDim.x + threadIdx.x;   // N * (K/32) threads
    int n    = t % N_DIM;
    int kb32 = t / N_DIM;                            // 0..127
    int g = kb32 >> 2;
    uint32_t zw = (uint32_t)qz[g * (N_DIM / 8) + (n >> 3)];
    int z = (int)((zw >> ((n & 7) * 4)) & 0xFu) + 1; // GPTQ zero+1
    float s = sc[(size_t)g * N_DIM + n];
    float v[32];
#pragma unroll
    for (int r = 0; r < 4; r++) {
        uint32_t w = (uint32_t)qw[(size_t)(kb32 * 4 + r) * N_DIM + n];
#pragma unroll
        for (int j = 0; j < 8; j++)
            v[r * 8 + j] = (float)((int)((w >> (4 * j)) & 0xFu) - z) * s;
    }
    uint4* dst = (uint4*)((char*)g_W + (size_t)(n >> 3) * 65536 +
                          (size_t)kb32 * 512 + (size_t)(n & 7) * 64);
#pragma unroll
    for (int tg = 0; tg < 4; tg++) {
        uint4 u;
        u.x = h2(v[tg * 2],      v[tg * 2 + 1]);      // b0 of k16_0
        u.y = h2(v[8 + tg * 2],  v[8 + tg * 2 + 1]);  // b1 of k16_0
        u.z = h2(v[16 + tg * 2], v[16 + tg * 2 + 1]); // b0 of k16_1
        u.w = h2(v[24 + tg * 2], v[24 + tg * 2 + 1]); // b1 of k16_1
        dst[tg] = u;
    }
}

// ------- kernel 2: x -> g_X (packed fp16 A units) -------
__global__ __launch_bounds__(256) void prep_x_kernel(const float* __restrict__ x) {
    int t = blockIdx.x * blockDim.x + threadIdx.x;   // 512*8*256 threads
    int k16 = t & 255;
    int pg  = t >> 8;
    int panel = pg >> 3, grp = pg & 7;
    int ra = panel * 16 + grp, rb = ra + 8;
    const float4* pa = (const float4*)(x + (size_t)ra * K_DIM + k16 * 16);
    const float4* pb = (const float4*)(x + (size_t)rb * K_DIM + k16 * 16);
    float A0[16], B0[16];
#pragma unroll
    for (int i = 0; i < 4; i++) {
        float4 va = pa[i], vb = pb[i];
        A0[i * 4 + 0] = va.x; A0[i * 4 + 1] = va.y; A0[i * 4 + 2] = va.z; A0[i * 4 + 3] = va.w;
        B0[i * 4 + 0] = vb.x; B0[i * 4 + 1] = vb.y; B0[i * 4 + 2] = vb.z; B0[i * 4 + 3] = vb.w;
    }
    uint4* dst = (uint4*)((char*)g_X + (size_t)panel * 131072 +
                          (size_t)k16 * 512 + (size_t)grp * 64);
#pragma unroll
    for (int tg = 0; tg < 4; tg++) {
        uint4 u;
        u.x = h2(A0[tg * 2],     A0[tg * 2 + 1]);      // a0 (row ra)
        u.y = h2(B0[tg * 2],     B0[tg * 2 + 1]);      // a1 (row rb)
        u.z = h2(A0[8 + tg * 2], A0[8 + tg * 2 + 1]);  // a2
        u.w = h2(B0[8 + tg * 2], B0[8 + tg * 2 + 1]);  // a3
        dst[tg] = u;
    }
}

// ------- kernel 3: fp16 HMMA GEMM  out[M,N] = X @ W -------
// 256 threads = 8 warps (2M x 4N), warp tile 64x64.
__global__ __launch_bounds__(256, 1) void gemm_kernel(float* __restrict__ out) {
    extern __shared__ __align__(16) char smem[];
    const uint4* sm4 = (const uint4*)smem;
    const uint32_t smem_addr = smem_u32(smem);
    const int tid = threadIdx.x;
    const int wid = tid >> 5, lid = tid & 31;
    const int grp = lid >> 2, tg = lid & 3;
    const int warpM = wid & 1;      // 2 x 64 = 128 M
    const int warpN = wid >> 1;     // 4 x 64 = 256 N

    const int band = blockIdx.x / (MBAND * NT);
    const int rem  = blockIdx.x % (MBAND * NT);
    const int nTile = rem / MBAND;
    const int mTile = band * MBAND + (rem % MBAND);

    // cp.async slots: A 1024 units + B 2048 units per stage; 12 per thread
    const char* aG[4]; uint32_t aS[4];
#pragma unroll
    for (int ii = 0; ii < 4; ii++) {
        int L = tid + 256 * ii;                 // 0..1023
        int p = L >> 7, k16s = (L >> 5) & 3, gA = (L >> 2) & 7, tA = L & 3;
        aG[ii] = (const char*)g_X + (size_t)(mTile * 8 + p) * 131072 +
                 (size_t)k16s * 512 + (size_t)(gA * 4 + tA) * 16;
        aS[ii] = (uint32_t)(L * 16);
    }
    const char* bG[8]; uint32_t bS[8];
#pragma unroll
    for (int ii = 0; ii < 8; ii++) {
        int L = tid + 256 * ii;                 // 0..2047
        int np = L >> 6, kb = (L >> 5) & 1, gB = (L >> 2) & 7, tB = L & 3;
        bG[ii] = (const char*)g_W + (size_t)(nTile * 32 + np) * 65536 +
                 (size_t)kb * 512 + (size_t)(gB * 4 + tB) * 16;
        bS[ii] = (uint32_t)(A_BYTES + L * 16);
    }

    // Prologue: stages 0..2  (per stage: A +2048 B, B +1024 B)
#pragma unroll
    for (int p = 0; p < NSTAGE - 1; p++) {
        uint32_t base = smem_addr + p * STAGE_BYTES;
#pragma unroll
        for (int i = 0; i < 4; i++) CPA16(base + aS[i], aG[i] + (size_t)p * 2048);
#pragma unroll
        for (int i = 0; i < 8; i++) CPA16(base + bS[i], bG[i] + (size_t)p * 1024);
        CP_COMMIT();
    }

    float acc[4][8][4];
#pragma unroll
    for (int i = 0; i < 4; i++)
#pragma unroll
        for (int j = 0; j < 8; j++)
#pragma unroll
            for (int e = 0; e < 4; e++) acc[i][j][e] = 0.0f;

    for (int kt = 0; kt < KT; kt++) {
        CP_WAIT2();                   // stage kt resident
        __syncthreads();              // all warps done with stage (kt-1) buffer

        int kl = kt + NSTAGE - 1;
        if (kl < KT) {
            uint32_t base = smem_addr + (kl & 3) * STAGE_BYTES;
#pragma unroll
            for (int i = 0; i < 4; i++) CPA16(base + aS[i], aG[i] + (size_t)kl * 2048);
#pragma unroll
            for (int i = 0; i < 8; i++) CPA16(base + bS[i], bG[i] + (size_t)kl * 1024);
        }
        CP_COMMIT();                  // empty groups near tail keep counts uniform

        const uint4* sA = sm4 + (kt & 3) * (STAGE_BYTES / 16);
        const uint4* sB = sA + A_U4;
#pragma unroll
        for (int kp = 0; kp < 2; kp++) {
            uint4 bf[8];
#pragma unroll
            for (int j = 0; j < 8; j++)
                bf[j] = sB[((warpN * 8 + j) * 2 + kp) * 32 + grp * 4 + tg];
#pragma unroll
            for (int half = 0; half < 2; half++) {
                const int ks = kp * 2 + half;
                uint4 af[4];
#pragma unroll
                for (int i = 0; i < 4; i++)
                    af[i] = sA[((warpM * 4 + i) * 4 + ks) * 32 + grp * 4 + tg];
#pragma unroll
                for (int i = 0; i < 4; i++)
#pragma unroll
                    for (int j = 0; j < 8; j++)
                        mma_f16(acc[i][j], af[i],
                                half ? bf[j].z : bf[j].x,
                                half ? bf[j].w : bf[j].y);
            }
        }
    }

    // Epilogue: direct STG from accumulators
#pragma unroll
    for (int i = 0; i < 4; i++) {
        size_t r0 = (size_t)mTile * BM + (warpM * 4 + i) * 16 + grp;
        size_t r1 = r0 + 8;
#pragma unroll
        for (int j = 0; j < 8; j++) {
            size_t cc = (size_t)nTile * BN + (warpN * 8 + j) * 8 + tg * 2;
            *(float2*)(out + r0 * N_DIM + cc) = make_float2(acc[i][j][0], acc[i][j][1]);
            *(float2*)(out + r1 * N_DIM + cc) = make_float2(acc[i][j][2], acc[i][j][3]);
        }
    }
}

// ---------------- launch ----------------
extern "C" void kernel_launch(void* const* d_in, const int* in_sizes, int n_in,
                              void* d_out, int out_size) {
    const float* x  = (const float*)d_in[0];
    const int*   qw = (const int*)d_in[1];
    const int*   qz = (const int*)d_in[2];
    const float* sc = (const float*)d_in[3];
    float* out = (float*)d_out;

    cudaFuncSetAttribute(gemm_kernel, cudaFuncAttributeMaxDynamicSharedMemorySize, SMEM_TOTAL);

    dequant_kernel<<<N_DIM * (K_DIM / 32) / 256, 256>>>(qw, qz, sc);
    prep_x_kernel<<<(M_DIM / 16) * 8 * (K_DIM / 16) / 256, 256>>>(x);

    gemm_kernel<<<MT * NT, 256, SMEM_TOTAL>>>(out);
}